// round 14
// baseline (speedup 1.0000x reference)
#include <cuda_runtime.h>
#include <cuda_fp16.h>
#include <math.h>
#include <stdint.h>

// Problem constants
#define BB 2
#define LL 2048
#define DD 2048
#define HH 16
#define HD 128
#define MROWS (BB * LL)        // 4096
#define D3 (3 * DD)            // 6144
#define D8 (8 * DD)            // 16384
#define D4 (4 * DD)            // 8192

// ---------------- scratch ----------------
__device__ float g_x1 [(size_t)MROWS * DD];
__device__ float g_cos[LL * 64];
__device__ float g_sin[LL * 64];

__device__ __align__(16) __half g_qkvh[(size_t)MROWS * D3];      // fp16 qkv
__device__ __align__(16) __half g_sh[(size_t)BB * HH * LL * LL]; // fp16 scores

__device__ __align__(16) __half g_ah[(size_t)MROWS * DD];
__device__ __align__(16) __half g_fh[(size_t)MROWS * D4];

__device__ __align__(16) __half g_qh[(size_t)BB * HH * LL * HD];
__device__ __align__(16) __half g_kh[(size_t)BB * HH * LL * HD];
__device__ __align__(16) __half g_vth[(size_t)BB * HH * HD * LL];
__device__ __align__(16) __half g_ph[(size_t)BB * HH * LL * LL];

__device__ __align__(16) __half g_WqkvT[(size_t)D3 * DD];
__device__ __align__(16) __half g_WoT[(size_t)DD * DD];
__device__ __align__(16) __half g_WpT[(size_t)D8 * DD];
__device__ __align__(16) __half g_WffT[(size_t)DD * D4];

// ================= helpers =================
__device__ __forceinline__ uint32_t smem_u32(const void* p) {
    uint32_t a;
    asm("{ .reg .u64 t; cvta.to.shared.u64 t, %1; cvt.u32.u64 %0, t; }" : "=r"(a) : "l"(p));
    return a;
}

#define CP_ASYNC16(dst, src) \
    asm volatile("cp.async.cg.shared.global [%0], [%1], 16;" :: "r"(dst), "l"(src) : "memory")
#define CP_COMMIT() asm volatile("cp.async.commit_group;" ::: "memory")
#define CP_WAIT1()  asm volatile("cp.async.wait_group 1;" ::: "memory")

#define LDSM4(r, addr) \
    asm volatile("ldmatrix.sync.aligned.m8n8.x4.shared.b16 {%0,%1,%2,%3}, [%4];" \
        : "=r"((r)[0]), "=r"((r)[1]), "=r"((r)[2]), "=r"((r)[3]) : "r"(addr))

#define MMA_F16(d, a, b0, b1) \
    asm volatile("mma.sync.aligned.m16n8k16.row.col.f32.f16.f16.f32 " \
        "{%0,%1,%2,%3}, {%4,%5,%6,%7}, {%8,%9}, {%0,%1,%2,%3};" \
        : "+f"((d)[0]), "+f"((d)[1]), "+f"((d)[2]), "+f"((d)[3]) \
        : "r"((a)[0]), "r"((a)[1]), "r"((a)[2]), "r"((a)[3]), "r"(b0), "r"(b1))

// ================= RoPE tables =================
__global__ void rope_table_kernel() {
    int p = blockIdx.x, i = threadIdx.x;
    double inv_freq = pow(10000.0, -(double)(2 * i) / (double)HD);
    double ang = (double)p * inv_freq;
    g_cos[p * 64 + i] = (float)cos(ang);
    g_sin[p * 64 + i] = (float)sin(ang);
}

// ================= RMSNorm -> fp16 =================
__global__ void rmsnorm_half_kernel(const float* __restrict__ x,
                                    const float* __restrict__ g,
                                    __half* __restrict__ o) {
    int row = blockIdx.x;
    const float* xr = x + (size_t)row * DD;
    float ss = 0.f;
    for (int c = threadIdx.x * 4; c < DD; c += blockDim.x * 4) {
        float4 v = *(const float4*)(xr + c);
        ss += v.x * v.x + v.y * v.y + v.z * v.z + v.w * v.w;
    }
    __shared__ float red[256];
    red[threadIdx.x] = ss;
    __syncthreads();
    for (int s = blockDim.x / 2; s > 0; s >>= 1) {
        if (threadIdx.x < s) red[threadIdx.x] += red[threadIdx.x + s];
        __syncthreads();
    }
    float scale = rsqrtf(red[0] / (float)DD + 1e-8f);
    for (int c = threadIdx.x * 4; c < DD; c += blockDim.x * 4) {
        float4 v = *(const float4*)(xr + c);
        float4 gv = *(const float4*)(g + c);
        *(__half2*)(o + (size_t)row * DD + c) = __halves2half2(
            __float2half_rn(v.x * scale * gv.x), __float2half_rn(v.y * scale * gv.y));
        *(__half2*)(o + (size_t)row * DD + c + 2) = __halves2half2(
            __float2half_rn(v.z * scale * gv.z), __float2half_rn(v.w * scale * gv.w));
    }
}

// ================= weight transpose -> fp16 =================
__global__ void transpose_half_kernel(const float* __restrict__ W,
                                      __half* __restrict__ T,
                                      int K, int N) {
    __shared__ float t[32][33];
    int n0 = blockIdx.x * 32, k0 = blockIdx.y * 32;
    int tx = threadIdx.x, ty = threadIdx.y;
#pragma unroll
    for (int r = 0; r < 4; r++) {
        int k = ty + r * 8;
        t[k][tx] = W[(size_t)(k0 + k) * N + n0 + tx];
    }
    __syncthreads();
#pragma unroll
    for (int r = 0; r < 4; r++) {
        int n = ty + r * 8;
        T[(size_t)(n0 + n) * K + k0 + tx] = __float2half_rn(t[tx][n]);
    }
}

// Wp transpose with gate/value interleave
__global__ void transpose_half_interleave_kernel(const float* __restrict__ W,
                                                 __half* __restrict__ T,
                                                 int K, int N) {
    __shared__ float t[32][33];
    int n0 = blockIdx.x * 32, k0 = blockIdx.y * 32;
    int tx = threadIdx.x, ty = threadIdx.y;
#pragma unroll
    for (int r = 0; r < 4; r++) {
        int k = ty + r * 8;
        t[k][tx] = W[(size_t)(k0 + k) * N + n0 + tx];
    }
    __syncthreads();
#pragma unroll
    for (int r = 0; r < 4; r++) {
        int n = ty + r * 8;
        int ncol = n0 + n;
        int rout = ((ncol & (D4 - 1)) << 1) | (ncol >> 13);
        T[(size_t)rout * K + k0 + tx] = __float2half_rn(t[tx][n]);
    }
}

// ====== fp16 GEMM: 128x128 tile, 256 thr, KC=64, 3-stage, register double-buffered ======
// MODE 0: fp32 C = acc + bias (+R).  MODE 1: SWIGLU -> fp16 Oh[M,N/2].
// MODE 2: fp16 Oh = acc + bias.
#define TM 128
#define TN 128
#define KC 64
#define A_OFF 0
#define B_OFF 16384
#define STG_BYTES 32768
#define GEMM_SMEM (3 * STG_BYTES)

template <int MODE>
__global__ void __launch_bounds__(256, 2) gemm_f16_kernel(
    const __half* __restrict__ A, const __half* __restrict__ B,
    const float* __restrict__ bias, const float* __restrict__ R,
    float* __restrict__ C, __half* __restrict__ Oh,
    int M, int N, int K)
{
    extern __shared__ char sm[];
    const int tid = threadIdx.x;
    const int lane = tid & 31;
    const int wid = tid >> 5;
    const int wm = wid & 3;
    const int wn = wid >> 2;
    const int bm = blockIdx.x * TM;
    const int bn = blockIdx.y * TN;
    const uint32_t smb = smem_u32(sm);

    const int rowA_base = wm * 32 + (lane & 15);
    const int rowB_base = wn * 64 + (lane & 7) + ((lane >> 4) << 3);
    const uint32_t xorw = (uint32_t)((lane & 6) << 3);
    // per-lane fixed column components for the two kk variants
    const uint32_t colA_lane = (uint32_t)((lane >> 4) << 4);
    const uint32_t colB_lane = (uint32_t)(((lane >> 3) & 1) << 4);

    float acc[2][8][4];
#pragma unroll
    for (int i = 0; i < 2; i++)
#pragma unroll
        for (int j = 0; j < 8; j++)
#pragma unroll
            for (int q = 0; q < 4; q++) acc[i][j][q] = 0.f;

    // operand double buffers (ping-pong across the 4 phases of a chunk)
    uint32_t abuf[2][2][4], bbuf[2][4][4];

    auto ld_phase = [&](uint32_t stg, int p, int buf) {
        const int kh = p >> 1, kk = p & 1;
        const uint32_t sa = stg + A_OFF + (uint32_t)(kh * 8192);
        const uint32_t sb = stg + B_OFF + (uint32_t)(kh * 8192);
        const uint32_t cbA = ((uint32_t)(kk * 32) + colA_lane) ^ xorw;
        const uint32_t cbB = ((uint32_t)(kk * 32) + colB_lane) ^ xorw;
#pragma unroll
        for (int mt = 0; mt < 2; mt++)
            LDSM4(abuf[buf][mt], sa + (uint32_t)((rowA_base + mt * 16) * 64) + cbA);
#pragma unroll
        for (int bt = 0; bt < 4; bt++)
            LDSM4(bbuf[buf][bt], sb + (uint32_t)((rowB_base + bt * 16) * 64) + cbB);
    };

    auto mma_phase = [&](int buf) {
#pragma unroll
        for (int mt = 0; mt < 2; mt++)
#pragma unroll
            for (int nt = 0; nt < 8; nt++) {
                const uint32_t* b = bbuf[buf][nt >> 1];
                if (nt & 1) MMA_F16(acc[mt][nt], abuf[buf][mt], b[2], b[3]);
                else        MMA_F16(acc[mt][nt], abuf[buf][mt], b[0], b[1]);
            }
    };

    // 2048 x 16B per chunk (A 128x64 + B 128x64), 8 per thread
    auto issue_chunk = [&](int k0, int stg) {
        const uint32_t sbase = smb + stg * STG_BYTES;
#pragma unroll
        for (int i = 0; i < 8; i++) {
            int u = tid + (i << 8);
            const __half* src;
            uint32_t roff;
            int row;
            if (u < 1024) { row = u >> 3;          src = A + (size_t)(bm + row) * K; roff = A_OFF; }
            else          { row = (u - 1024) >> 3; src = B + (size_t)(bn + row) * K; roff = B_OFF; }
            int s8 = u & 7;
            int kh = s8 >> 2;
            int seg = s8 & 3;
            uint32_t dst = sbase + roff + (uint32_t)(kh * 8192) + (uint32_t)(row * 64) +
                           (((uint32_t)(seg * 16)) ^ ((uint32_t)((row & 6) << 3)));
            CP_ASYNC16(dst, src + k0 + kh * 32 + seg * 8);
        }
        CP_COMMIT();
    };

    const int NC = K / KC;
    issue_chunk(0, 0);
    issue_chunk(KC, 1);

    for (int c = 0; c < NC; ++c) {
        CP_WAIT1();
        __syncthreads();
        if (c + 2 < NC) issue_chunk((c + 2) * KC, (c + 2) % 3);
        else CP_COMMIT();

        const uint32_t stg = smb + (uint32_t)((c % 3) * STG_BYTES);

        // software-pipelined phases: load p+1 before issuing MMAs of p
        ld_phase(stg, 0, 0);
#pragma unroll
        for (int p = 0; p < 4; p++) {
            if (p < 3) ld_phase(stg, p + 1, (p + 1) & 1);
            mma_phase(p & 1);
        }
    }

    // ---- epilogue ----
    if (MODE == 1) {
        const int outN = N >> 1;
#pragma unroll
        for (int mt = 0; mt < 2; mt++) {
            const int m = bm + wm * 32 + mt * 16 + (lane >> 2);
#pragma unroll
            for (int nt = 0; nt < 8; nt++) {
                const int nperm = bn + wn * 64 + nt * 8 + ((lane & 3) << 1);
                const int i = nperm >> 1;
                float bg = bias[i];
                float bv = bias[outN + i];
                float g0 = acc[mt][nt][0] + bg, v0 = acc[mt][nt][1] + bv;
                float g1 = acc[mt][nt][2] + bg, v1 = acc[mt][nt][3] + bv;
                float r0 = g0 / (1.f + expf(-g0)) * v0;
                float r1 = g1 / (1.f + expf(-g1)) * v1;
                Oh[(size_t)m * outN + i] = __float2half_rn(r0);
                Oh[(size_t)(m + 8) * outN + i] = __float2half_rn(r1);
            }
        }
    } else if (MODE == 2) {
#pragma unroll
        for (int mt = 0; mt < 2; mt++) {
            const int m = bm + wm * 32 + mt * 16 + (lane >> 2);
#pragma unroll
            for (int nt = 0; nt < 8; nt++) {
                const int n = bn + wn * 64 + nt * 8 + ((lane & 3) << 1);
                float2 b2 = *(const float2*)(bias + n);
                *(__half2*)(Oh + (size_t)m * N + n) = __halves2half2(
                    __float2half_rn(acc[mt][nt][0] + b2.x),
                    __float2half_rn(acc[mt][nt][1] + b2.y));
                *(__half2*)(Oh + (size_t)(m + 8) * N + n) = __halves2half2(
                    __float2half_rn(acc[mt][nt][2] + b2.x),
                    __float2half_rn(acc[mt][nt][3] + b2.y));
            }
        }
    } else {
#pragma unroll
        for (int mt = 0; mt < 2; mt++) {
            const int m = bm + wm * 32 + mt * 16 + (lane >> 2);
#pragma unroll
            for (int nt = 0; nt < 8; nt++) {
                const int n = bn + wn * 64 + nt * 8 + ((lane & 3) << 1);
                float2 b2 = *(const float2*)(bias + n);
                float2 o0, o1;
                o0.x = acc[mt][nt][0] + b2.x;
                o0.y = acc[mt][nt][1] + b2.y;
                o1.x = acc[mt][nt][2] + b2.x;
                o1.y = acc[mt][nt][3] + b2.y;
                if (R) {
                    float2 r0 = *(const float2*)(R + (size_t)m * N + n);
                    float2 r1 = *(const float2*)(R + (size_t)(m + 8) * N + n);
                    o0.x += r0.x; o0.y += r0.y;
                    o1.x += r1.x; o1.y += r1.y;
                }
                *(float2*)(C + (size_t)m * N + n) = o0;
                *(float2*)(C + (size_t)(m + 8) * N + n) = o1;
            }
        }
    }
}

// ================= RoPE: qkv fp16 -> fp16 q,k in [B,H,L,HD] =================
__global__ void rope_apply_half_kernel() {
    int idx = blockIdx.x * blockDim.x + threadIdx.x;
    if (idx >= BB * LL * HH * 64) return;
    int d = idx & 63;
    int h = (idx >> 6) & (HH - 1);
    int bl = idx >> 10;
    int b = bl >> 11;
    int l = bl & (LL - 1);
    float c = g_cos[l * 64 + d];
    float s = g_sin[l * 64 + d];
    size_t src = (size_t)bl * D3 + h * HD + d;
    size_t dst = ((size_t)(b * HH + h) * LL + l) * HD + d;

    float q1 = __half2float(g_qkvh[src]), q2 = __half2float(g_qkvh[src + 64]);
    g_qh[dst]      = __float2half_rn(q1 * c - q2 * s);
    g_qh[dst + 64] = __float2half_rn(q2 * c + q1 * s);

    size_t ks = src + DD;
    float k1 = __half2float(g_qkvh[ks]), k2 = __half2float(g_qkvh[ks + 64]);
    g_kh[dst]      = __float2half_rn(k1 * c - k2 * s);
    g_kh[dst + 64] = __float2half_rn(k2 * c + k1 * s);
}

// ================= V transpose (fp16) -> [B,H,HD,L] =================
__global__ void v_transpose_kernel() {
    __shared__ __half t[32][33];
    int l0 = blockIdx.x * 32, d0 = blockIdx.y * 32, bh = blockIdx.z;
    int b = bh >> 4, h = bh & 15;
    int tx = threadIdx.x, ty = threadIdx.y;
#pragma unroll
    for (int r = 0; r < 4; r++) {
        int l = ty + r * 8;
        t[l][tx] = g_qkvh[(size_t)(b * LL + l0 + l) * D3 + 2 * DD + h * HD + d0 + tx];
    }
    __syncthreads();
#pragma unroll
    for (int r = 0; r < 4; r++) {
        int d = ty + r * 8;
        g_vth[((size_t)bh * HD + d0 + d) * LL + l0 + tx] = t[tx][d];
    }
}

// ================= attention scores (fp16) -> fp16 g_sh =================
#define ATT_STG 16384
#define ATT_SMEM (3 * ATT_STG)

__global__ void __launch_bounds__(256, 2) attn_scores_mma_kernel() {
    extern __shared__ char sm[];
    const int jb = blockIdx.x, ib = blockIdx.y, bh = blockIdx.z;
    if (jb > ib) return;
    const int tid = threadIdx.x, lane = tid & 31, wid = tid >> 5;
    const int wm = wid & 3, wn = wid >> 2;
    const uint32_t smb = smem_u32(sm);

    const __half* Qh = g_qh + ((size_t)bh * LL + ib * 128) * HD;
    const __half* Kh = g_kh + ((size_t)bh * LL + jb * 128) * HD;

    const int rowA_base = wm * 32 + (lane & 15);
    const int rowB_base = wn * 64 + (lane & 7) + ((lane >> 4) << 3);
    const uint32_t xorw = (uint32_t)((lane & 6) << 3);

    float acc[2][8][4];
#pragma unroll
    for (int i = 0; i < 2; i++)
#pragma unroll
        for (int j = 0; j < 8; j++)
#pragma unroll
            for (int q = 0; q < 4; q++) acc[i][j][q] = 0.f;

    auto issue = [&](int c, int stg) {
        const uint32_t sb = smb + (uint32_t)(stg * ATT_STG);
        const int k0 = c * 32;
#pragma unroll
        for (int i = 0; i < 4; i++) {
            int u = tid + (i << 8);
            int row = (u >> 2) & 127;
            int seg = u & 3;
            const __half* src = (u < 512) ? Qh : Kh;
            uint32_t roff = (u < 512) ? 0u : 8192u;
            uint32_t dst = sb + roff + (uint32_t)(row * 64) +
                           (((uint32_t)(seg * 16)) ^ ((uint32_t)((row & 6) << 3)));
            CP_ASYNC16(dst, src + (size_t)row * HD + k0 + seg * 8);
        }
        CP_COMMIT();
    };

    issue(0, 0);
    issue(1, 1);
#pragma unroll 1
    for (int c = 0; c < 4; c++) {
        CP_WAIT1();
        __syncthreads();
        if (c + 2 < 4) issue(c + 2, (c + 2) % 3);
        else CP_COMMIT();
        const uint32_t stg = smb + (uint32_t)((c % 3) * ATT_STG);
#pragma unroll
        for (int kk = 0; kk < 2; kk++) {
            const uint32_t cbA = ((uint32_t)(kk * 32 + ((lane >> 4) << 4))) ^ xorw;
            const uint32_t cbB = ((uint32_t)(kk * 32 + (((lane >> 3) & 1) << 4))) ^ xorw;
            uint32_t ah[2][4], b4[4][4];
#pragma unroll
            for (int mt = 0; mt < 2; mt++)
                LDSM4(ah[mt], stg + 0 + (uint32_t)((rowA_base + mt * 16) * 64) + cbA);
#pragma unroll
            for (int bt = 0; bt < 4; bt++)
                LDSM4(b4[bt], stg + 8192 + (uint32_t)((rowB_base + bt * 16) * 64) + cbB);
#pragma unroll
            for (int mt = 0; mt < 2; mt++)
#pragma unroll
                for (int nt = 0; nt < 8; nt++) {
                    const uint32_t* b = b4[nt >> 1];
                    if (nt & 1) MMA_F16(acc[mt][nt], ah[mt], b[2], b[3]);
                    else        MMA_F16(acc[mt][nt], ah[mt], b[0], b[1]);
                }
        }
    }

    const float scale = 0.08838834764831845f;
#pragma unroll
    for (int mt = 0; mt < 2; mt++) {
        const int i0 = ib * 128 + wm * 32 + mt * 16 + (lane >> 2);
#pragma unroll
        for (int nt = 0; nt < 8; nt++) {
            const int j0 = jb * 128 + wn * 64 + nt * 8 + ((lane & 3) << 1);
            float s00 = (j0     <= i0)     ? acc[mt][nt][0] * scale : -30000.f;
            float s01 = (j0 + 1 <= i0)     ? acc[mt][nt][1] * scale : -30000.f;
            float s10 = (j0     <= i0 + 8) ? acc[mt][nt][2] * scale : -30000.f;
            float s11 = (j0 + 1 <= i0 + 8) ? acc[mt][nt][3] * scale : -30000.f;
            *(__half2*)(g_sh + ((size_t)bh * LL + i0) * LL + j0) =
                __halves2half2(__float2half_rn(s00), __float2half_rn(s01));
            *(__half2*)(g_sh + ((size_t)bh * LL + i0 + 8) * LL + j0) =
                __halves2half2(__float2half_rn(s10), __float2half_rn(s11));
        }
    }
}

// ========== row softmax (fp16 in) -> fp16 P ==========
__global__ void softmax_kernel() {
    int r = blockIdx.x;
    int i = r & (LL - 1);
    int len = ((i >> 6) + 1) << 6;
    int len2 = ((i >> 7) + 1) << 7;
    const __half* p = g_sh + (size_t)r * LL;
    __half* ph = g_ph + (size_t)r * LL;
    __shared__ float red[128];

    float m = -1e30f;
    for (int c = threadIdx.x * 4; c < len; c += 512) {
        __half2 v0 = *(const __half2*)(p + c);
        __half2 v1 = *(const __half2*)(p + c + 2);
        float a0 = __low2float(v0), a1 = __high2float(v0);
        float a2 = __low2float(v1), a3 = __high2float(v1);
        m = fmaxf(m, fmaxf(fmaxf(a0, a1), fmaxf(a2, a3)));
    }
    red[threadIdx.x] = m;
    __syncthreads();
    for (int s = 64; s > 0; s >>= 1) {
        if (threadIdx.x < s) red[threadIdx.x] = fmaxf(red[threadIdx.x], red[threadIdx.x + s]);
        __syncthreads();
    }
    m = red[0];
    __syncthreads();

    float sum = 0.f;
    for (int c = threadIdx.x * 4; c < len; c += 512) {
        __half2 v0 = *(const __half2*)(p + c);
        __half2 v1 = *(const __half2*)(p + c + 2);
        sum += expf(__low2float(v0) - m) + expf(__high2float(v0) - m)
             + expf(__low2float(v1) - m) + expf(__high2float(v1) - m);
    }
    red[threadIdx.x] = sum;
    __syncthreads();
    for (int s = 64; s > 0; s >>= 1) {
        if (threadIdx.x < s) red[threadIdx.x] += red[threadIdx.x + s];
        __syncthreads();
    }
    float inv = 1.f / red[0];
    for (int c = threadIdx.x * 4; c < len; c += 512) {
        __half2 v0 = *(const __half2*)(p + c);
        __half2 v1 = *(const __half2*)(p + c + 2);
        *(__half2*)(ph + c) = __halves2half2(
            __float2half_rn(expf(__low2float(v0) - m) * inv),
            __float2half_rn(expf(__high2float(v0) - m) * inv));
        *(__half2*)(ph + c + 2) = __halves2half2(
            __float2half_rn(expf(__low2float(v1) - m) * inv),
            __float2half_rn(expf(__high2float(v1) - m) * inv));
    }
    __half2 z = __halves2half2(__float2half_rn(0.f), __float2half_rn(0.f));
    for (int c = len + threadIdx.x * 4; c < len2; c += 512) {
        *(__half2*)(ph + c) = z;
        *(__half2*)(ph + c + 2) = z;
    }
}

// ================= O = P @ V (fp16) -> fp16 o =================
__global__ void __launch_bounds__(256, 2) attn_pv_mma_kernel() {
    extern __shared__ char sm[];
    const int ib = blockIdx.x, bh = blockIdx.y;
    const int b = bh >> 4, h = bh & 15;
    const int tid = threadIdx.x, lane = tid & 31, wid = tid >> 5;
    const int wm = wid & 3, wn = wid >> 2;
    const uint32_t smb = smem_u32(sm);

    const __half* Ph = g_ph + ((size_t)bh * LL + ib * 128) * LL;
    const __half* Vh = g_vth + (size_t)bh * HD * LL;

    const int rowA_base = wm * 32 + (lane & 15);
    const int rowB_base = wn * 64 + (lane & 7) + ((lane >> 4) << 3);
    const uint32_t xorw = (uint32_t)((lane & 6) << 3);

    float acc[2][8][4];
#pragma unroll
    for (int i = 0; i < 2; i++)
#pragma unroll
        for (int j = 0; j < 8; j++)
#pragma unroll
            for (int q = 0; q < 4; q++) acc[i][j][q] = 0.f;

    auto issue = [&](int c, int stg) {
        const uint32_t sb = smb + (uint32_t)(stg * ATT_STG);
        const int j0 = c * 32;
#pragma unroll
        for (int i = 0; i < 4; i++) {
            int u = tid + (i << 8);
            int row = (u >> 2) & 127;
            int seg = u & 3;
            const __half* src = (u < 512) ? Ph : Vh;
            uint32_t roff = (u < 512) ? 0u : 8192u;
            uint32_t dst = sb + roff + (uint32_t)(row * 64) +
                           (((uint32_t)(seg * 16)) ^ ((uint32_t)((row & 6) << 3)));
            CP_ASYNC16(dst, src + (size_t)row * LL + j0 + seg * 8);
        }
        CP_COMMIT();
    };

    const int NC = (ib + 1) * 4;
    issue(0, 0);
    issue(1, 1);
#pragma unroll 1
    for (int c = 0; c < NC; c++) {
        CP_WAIT1();
        __syncthreads();
        if (c + 2 < NC) issue(c + 2, (c + 2) % 3);
        else CP_COMMIT();
        const uint32_t stg = smb + (uint32_t)((c % 3) * ATT_STG);
#pragma unroll
        for (int kk = 0; kk < 2; kk++) {
            const uint32_t cbA = ((uint32_t)(kk * 32 + ((lane >> 4) << 4))) ^ xorw;
            const uint32_t cbB = ((uint32_t)(kk * 32 + (((lane >> 3) & 1) << 4))) ^ xorw;
            uint32_t ah[2][4], b4[4][4];
#pragma unroll
            for (int mt = 0; mt < 2; mt++)
                LDSM4(ah[mt], stg + 0 + (uint32_t)((rowA_base + mt * 16) * 64) + cbA);
#pragma unroll
            for (int bt = 0; bt < 4; bt++)
                LDSM4(b4[bt], stg + 8192 + (uint32_t)((rowB_base + bt * 16) * 64) + cbB);
#pragma unroll
            for (int mt = 0; mt < 2; mt++)
#pragma unroll
                for (int nt = 0; nt < 8; nt++) {
                    const uint32_t* bb = b4[nt >> 1];
                    if (nt & 1) MMA_F16(acc[mt][nt], ah[mt], bb[2], bb[3]);
                    else        MMA_F16(acc[mt][nt], ah[mt], bb[0], bb[1]);
                }
        }
    }

#pragma unroll
    for (int mt = 0; mt < 2; mt++) {
        const int qi = ib * 128 + wm * 32 + mt * 16 + (lane >> 2);
#pragma unroll
        for (int nt = 0; nt < 8; nt++) {
            const int d = wn * 64 + nt * 8 + ((lane & 3) << 1);
            size_t base0 = (size_t)(b * LL + qi) * DD + h * HD + d;
            size_t base1 = (size_t)(b * LL + qi + 8) * DD + h * HD + d;
            *(__half2*)(g_ah + base0) = __halves2half2(
                __float2half_rn(acc[mt][nt][0]), __float2half_rn(acc[mt][nt][1]));
            *(__half2*)(g_ah + base1) = __halves2half2(
                __float2half_rn(acc[mt][nt][2]), __float2half_rn(acc[mt][nt][3]));
        }
    }
}

// ================= launch =================
extern "C" void kernel_launch(void* const* d_in, const int* in_sizes, int n_in,
                              void* d_out, int out_size) {
    const float* x    = (const float*)d_in[0];
    const float* Wqkv = (const float*)d_in[1];
    const float* bqkv = (const float*)d_in[2];
    const float* Wo   = (const float*)d_in[3];
    const float* bo   = (const float*)d_in[4];
    const float* g1   = (const float*)d_in[5];
    const float* g2   = (const float*)d_in[6];
    const float* Wp   = (const float*)d_in[7];
    const float* bp   = (const float*)d_in[8];
    const float* Wff  = (const float*)d_in[9];
    const float* bff  = (const float*)d_in[10];
    float* out = (float*)d_out;

    __half *ah, *fh, *wq, *wo, *wp, *wf, *qkvh;
    float *x1;
    cudaGetSymbolAddress((void**)&ah,   g_ah);
    cudaGetSymbolAddress((void**)&fh,   g_fh);
    cudaGetSymbolAddress((void**)&wq,   g_WqkvT);
    cudaGetSymbolAddress((void**)&wo,   g_WoT);
    cudaGetSymbolAddress((void**)&wp,   g_WpT);
    cudaGetSymbolAddress((void**)&wf,   g_WffT);
    cudaGetSymbolAddress((void**)&qkvh, g_qkvh);
    cudaGetSymbolAddress((void**)&x1,   g_x1);

    cudaFuncSetAttribute(gemm_f16_kernel<0>,
                         cudaFuncAttributeMaxDynamicSharedMemorySize, GEMM_SMEM);
    cudaFuncSetAttribute(gemm_f16_kernel<1>,
                         cudaFuncAttributeMaxDynamicSharedMemorySize, GEMM_SMEM);
    cudaFuncSetAttribute(gemm_f16_kernel<2>,
                         cudaFuncAttributeMaxDynamicSharedMemorySize, GEMM_SMEM);
    cudaFuncSetAttribute(attn_scores_mma_kernel,
                         cudaFuncAttributeMaxDynamicSharedMemorySize, ATT_SMEM);
    cudaFuncSetAttribute(attn_pv_mma_kernel,
                         cudaFuncAttributeMaxDynamicSharedMemorySize, ATT_SMEM);

    dim3 tb(32, 8);

    rope_table_kernel<<<LL, 64>>>();
    transpose_half_kernel<<<dim3(D3 / 32, DD / 32), tb>>>(Wqkv, wq, DD, D3);
    rmsnorm_half_kernel<<<MROWS, 256>>>(x, g1, ah);

    // qkv (fp16 out) = h @ Wqkv + bqkv   (launch #4 — profiled)
    gemm_f16_kernel<2><<<dim3(MROWS / TM, D3 / TN), 256, GEMM_SMEM>>>(
        ah, wq, bqkv, nullptr, nullptr, qkvh, MROWS, D3, DD);

    {
        int total = BB * LL * HH * 64;
        rope_apply_half_kernel<<<(total + 255) / 256, 256>>>();
    }
    v_transpose_kernel<<<dim3(LL / 32, HD / 32, BB * HH), tb>>>();
    attn_scores_mma_kernel<<<dim3(LL / 128, LL / 128, BB * HH), 256, ATT_SMEM>>>();
    softmax_kernel<<<BB * HH * LL, 128>>>();
    attn_pv_mma_kernel<<<dim3(LL / 128, BB * HH), 256, ATT_SMEM>>>();

    transpose_half_kernel<<<dim3(DD / 32, DD / 32), tb>>>(Wo, wo, DD, DD);
    gemm_f16_kernel<0><<<dim3(MROWS / TM, DD / TN), 256, GEMM_SMEM>>>(
        ah, wo, bo, x, x1, nullptr, MROWS, DD, DD);

    rmsnorm_half_kernel<<<MROWS, 256>>>(x1, g2, ah);

    transpose_half_interleave_kernel<<<dim3(D8 / 32, DD / 32), tb>>>(Wp, wp, DD, D8);
    gemm_f16_kernel<1><<<dim3(MROWS / TM, D8 / TN), 256, GEMM_SMEM>>>(
        ah, wp, bp, nullptr, nullptr, fh, MROWS, D8, DD);

    transpose_half_kernel<<<dim3(DD / 32, D4 / 32), tb>>>(Wff, wf, D4, DD);
    gemm_f16_kernel<0><<<dim3(MROWS / TM, DD / TN), 256, GEMM_SMEM>>>(
        fh, wf, bff, x1, out, nullptr, MROWS, DD, D4);
}

// round 16
// speedup vs baseline: 1.0288x; 1.0288x over previous
#include <cuda_runtime.h>
#include <cuda_fp16.h>
#include <math.h>
#include <stdint.h>

// Problem constants
#define BB 2
#define LL 2048
#define DD 2048
#define HH 16
#define HD 128
#define MROWS (BB * LL)        // 4096
#define D3 (3 * DD)            // 6144
#define D8 (8 * DD)            // 16384
#define D4 (4 * DD)            // 8192

// ---------------- scratch ----------------
__device__ float g_x1 [(size_t)MROWS * DD];
__device__ float g_cos[LL * 64];
__device__ float g_sin[LL * 64];

__device__ __align__(16) __half g_qkvh[(size_t)MROWS * D3];      // fp16 qkv
__device__ __align__(16) __half g_sh[(size_t)BB * HH * LL * LL]; // fp16 scores

__device__ __align__(16) __half g_ah[(size_t)MROWS * DD];
__device__ __align__(16) __half g_fh[(size_t)MROWS * D4];

__device__ __align__(16) __half g_qh[(size_t)BB * HH * LL * HD];
__device__ __align__(16) __half g_kh[(size_t)BB * HH * LL * HD];
__device__ __align__(16) __half g_vth[(size_t)BB * HH * HD * LL];

// flash-softmax partials: [bh][row][jb2] with jb2 = jb*2 + wn (32 slots)
__device__ float g_pmax[(size_t)BB * HH * LL * 32];
__device__ float g_psum[(size_t)BB * HH * LL * 32];
__device__ float g_rowm[(size_t)BB * HH * LL];
__device__ float g_rowinv[(size_t)BB * HH * LL];

__device__ __align__(16) __half g_WqkvT[(size_t)D3 * DD];
__device__ __align__(16) __half g_WoT[(size_t)DD * DD];
__device__ __align__(16) __half g_WpT[(size_t)D8 * DD];
__device__ __align__(16) __half g_WffT[(size_t)DD * D4];

// ================= helpers =================
__device__ __forceinline__ uint32_t smem_u32(const void* p) {
    uint32_t a;
    asm("{ .reg .u64 t; cvta.to.shared.u64 t, %1; cvt.u32.u64 %0, t; }" : "=r"(a) : "l"(p));
    return a;
}

#define CP_ASYNC16(dst, src) \
    asm volatile("cp.async.cg.shared.global [%0], [%1], 16;" :: "r"(dst), "l"(src) : "memory")
#define CP_COMMIT() asm volatile("cp.async.commit_group;" ::: "memory")
#define CP_WAIT1()  asm volatile("cp.async.wait_group 1;" ::: "memory")

#define LDSM4(r, addr) \
    asm volatile("ldmatrix.sync.aligned.m8n8.x4.shared.b16 {%0,%1,%2,%3}, [%4];" \
        : "=r"((r)[0]), "=r"((r)[1]), "=r"((r)[2]), "=r"((r)[3]) : "r"(addr))

#define MMA_F16(d, a, b0, b1) \
    asm volatile("mma.sync.aligned.m16n8k16.row.col.f32.f16.f16.f32 " \
        "{%0,%1,%2,%3}, {%4,%5,%6,%7}, {%8,%9}, {%0,%1,%2,%3};" \
        : "+f"((d)[0]), "+f"((d)[1]), "+f"((d)[2]), "+f"((d)[3]) \
        : "r"((a)[0]), "r"((a)[1]), "r"((a)[2]), "r"((a)[3]), "r"(b0), "r"(b1))

#define STS128(dst, v) \
    asm volatile("st.shared.v4.b32 [%0], {%1,%2,%3,%4};" \
        :: "r"(dst), "r"((v).x), "r"((v).y), "r"((v).z), "r"((v).w) : "memory")

// ================= RoPE tables =================
__global__ void rope_table_kernel() {
    int p = blockIdx.x, i = threadIdx.x;
    double inv_freq = pow(10000.0, -(double)(2 * i) / (double)HD);
    double ang = (double)p * inv_freq;
    g_cos[p * 64 + i] = (float)cos(ang);
    g_sin[p * 64 + i] = (float)sin(ang);
}

// ================= RMSNorm -> fp16 =================
__global__ void rmsnorm_half_kernel(const float* __restrict__ x,
                                    const float* __restrict__ g,
                                    __half* __restrict__ o) {
    int row = blockIdx.x;
    const float* xr = x + (size_t)row * DD;
    float ss = 0.f;
    for (int c = threadIdx.x * 4; c < DD; c += blockDim.x * 4) {
        float4 v = *(const float4*)(xr + c);
        ss += v.x * v.x + v.y * v.y + v.z * v.z + v.w * v.w;
    }
    __shared__ float red[256];
    red[threadIdx.x] = ss;
    __syncthreads();
    for (int s = blockDim.x / 2; s > 0; s >>= 1) {
        if (threadIdx.x < s) red[threadIdx.x] += red[threadIdx.x + s];
        __syncthreads();
    }
    float scale = rsqrtf(red[0] / (float)DD + 1e-8f);
    for (int c = threadIdx.x * 4; c < DD; c += blockDim.x * 4) {
        float4 v = *(const float4*)(xr + c);
        float4 gv = *(const float4*)(g + c);
        *(__half2*)(o + (size_t)row * DD + c) = __halves2half2(
            __float2half_rn(v.x * scale * gv.x), __float2half_rn(v.y * scale * gv.y));
        *(__half2*)(o + (size_t)row * DD + c + 2) = __halves2half2(
            __float2half_rn(v.z * scale * gv.z), __float2half_rn(v.w * scale * gv.w));
    }
}

// ================= weight transpose -> fp16 =================
__global__ void transpose_half_kernel(const float* __restrict__ W,
                                      __half* __restrict__ T,
                                      int K, int N) {
    __shared__ float t[32][33];
    int n0 = blockIdx.x * 32, k0 = blockIdx.y * 32;
    int tx = threadIdx.x, ty = threadIdx.y;
#pragma unroll
    for (int r = 0; r < 4; r++) {
        int k = ty + r * 8;
        t[k][tx] = W[(size_t)(k0 + k) * N + n0 + tx];
    }
    __syncthreads();
#pragma unroll
    for (int r = 0; r < 4; r++) {
        int n = ty + r * 8;
        T[(size_t)(n0 + n) * K + k0 + tx] = __float2half_rn(t[tx][n]);
    }
}

// Wp transpose with gate/value interleave
__global__ void transpose_half_interleave_kernel(const float* __restrict__ W,
                                                 __half* __restrict__ T,
                                                 int K, int N) {
    __shared__ float t[32][33];
    int n0 = blockIdx.x * 32, k0 = blockIdx.y * 32;
    int tx = threadIdx.x, ty = threadIdx.y;
#pragma unroll
    for (int r = 0; r < 4; r++) {
        int k = ty + r * 8;
        t[k][tx] = W[(size_t)(k0 + k) * N + n0 + tx];
    }
    __syncthreads();
#pragma unroll
    for (int r = 0; r < 4; r++) {
        int n = ty + r * 8;
        int ncol = n0 + n;
        int rout = ((ncol & (D4 - 1)) << 1) | (ncol >> 13);
        T[(size_t)rout * K + k0 + tx] = __float2half_rn(t[tx][n]);
    }
}

// ====== fp16 GEMM: 128x128 tile, 256 thr, KC=64, 3-stage (R13-proven loop) ======
#define TM 128
#define TN 128
#define KC 64
#define A_OFF 0
#define B_OFF 16384
#define STG_BYTES 32768
#define GEMM_SMEM (3 * STG_BYTES)

template <int MODE>
__global__ void __launch_bounds__(256, 2) gemm_f16_kernel(
    const __half* __restrict__ A, const __half* __restrict__ B,
    const float* __restrict__ bias, const float* __restrict__ R,
    float* __restrict__ C, __half* __restrict__ Oh,
    int M, int N, int K)
{
    extern __shared__ char sm[];
    const int tid = threadIdx.x;
    const int lane = tid & 31;
    const int wid = tid >> 5;
    const int wm = wid & 3;
    const int wn = wid >> 2;
    const int bm = blockIdx.x * TM;
    const int bn = blockIdx.y * TN;
    const uint32_t smb = smem_u32(sm);

    const int rowA_base = wm * 32 + (lane & 15);
    const int rowB_base = wn * 64 + (lane & 7) + ((lane >> 4) << 3);
    const uint32_t xorw = (uint32_t)((lane & 6) << 3);

    float acc[2][8][4];
#pragma unroll
    for (int i = 0; i < 2; i++)
#pragma unroll
        for (int j = 0; j < 8; j++)
#pragma unroll
            for (int q = 0; q < 4; q++) acc[i][j][q] = 0.f;

    auto issue_chunk = [&](int k0, int stg) {
        const uint32_t sbase = smb + stg * STG_BYTES;
#pragma unroll
        for (int i = 0; i < 8; i++) {
            int u = tid + (i << 8);
            const __half* src;
            uint32_t roff;
            int row;
            if (u < 1024) { row = u >> 3;          src = A + (size_t)(bm + row) * K; roff = A_OFF; }
            else          { row = (u - 1024) >> 3; src = B + (size_t)(bn + row) * K; roff = B_OFF; }
            int s8 = u & 7;
            int kh = s8 >> 2;
            int seg = s8 & 3;
            uint32_t dst = sbase + roff + (uint32_t)(kh * 8192) + (uint32_t)(row * 64) +
                           (((uint32_t)(seg * 16)) ^ ((uint32_t)((row & 6) << 3)));
            CP_ASYNC16(dst, src + k0 + kh * 32 + seg * 8);
        }
        CP_COMMIT();
    };

    const int NC = K / KC;
    issue_chunk(0, 0);
    issue_chunk(KC, 1);

    for (int c = 0; c < NC; ++c) {
        CP_WAIT1();
        __syncthreads();
        if (c + 2 < NC) issue_chunk((c + 2) * KC, (c + 2) % 3);
        else CP_COMMIT();

        const uint32_t stg = smb + (uint32_t)((c % 3) * STG_BYTES);

#pragma unroll
        for (int kh = 0; kh < 2; kh++) {
            const uint32_t sa = stg + A_OFF + (uint32_t)(kh * 8192);
            const uint32_t sb = stg + B_OFF + (uint32_t)(kh * 8192);
#pragma unroll
            for (int kk = 0; kk < 2; kk++) {
                const uint32_t cbA = ((uint32_t)(kk * 32 + ((lane >> 4) << 4))) ^ xorw;
                const uint32_t cbB = ((uint32_t)(kk * 32 + (((lane >> 3) & 1) << 4))) ^ xorw;

                uint32_t ah[2][4], b4[4][4];
#pragma unroll
                for (int mt = 0; mt < 2; mt++)
                    LDSM4(ah[mt], sa + (uint32_t)((rowA_base + mt * 16) * 64) + cbA);
#pragma unroll
                for (int bt = 0; bt < 4; bt++)
                    LDSM4(b4[bt], sb + (uint32_t)((rowB_base + bt * 16) * 64) + cbB);
#pragma unroll
                for (int mt = 0; mt < 2; mt++)
#pragma unroll
                    for (int nt = 0; nt < 8; nt++) {
                        const uint32_t* b = b4[nt >> 1];
                        if (nt & 1) MMA_F16(acc[mt][nt], ah[mt], b[2], b[3]);
                        else        MMA_F16(acc[mt][nt], ah[mt], b[0], b[1]);
                    }
            }
        }
    }

    // ---- epilogue ----
    if (MODE == 1) {
        const int outN = N >> 1;
#pragma unroll
        for (int mt = 0; mt < 2; mt++) {
            const int m = bm + wm * 32 + mt * 16 + (lane >> 2);
#pragma unroll
            for (int nt = 0; nt < 8; nt++) {
                const int nperm = bn + wn * 64 + nt * 8 + ((lane & 3) << 1);
                const int i = nperm >> 1;
                float bg = bias[i];
                float bv = bias[outN + i];
                float g0 = acc[mt][nt][0] + bg, v0 = acc[mt][nt][1] + bv;
                float g1 = acc[mt][nt][2] + bg, v1 = acc[mt][nt][3] + bv;
                float r0 = g0 / (1.f + expf(-g0)) * v0;
                float r1 = g1 / (1.f + expf(-g1)) * v1;
                Oh[(size_t)m * outN + i] = __float2half_rn(r0);
                Oh[(size_t)(m + 8) * outN + i] = __float2half_rn(r1);
            }
        }
    } else if (MODE == 2) {
#pragma unroll
        for (int mt = 0; mt < 2; mt++) {
            const int m = bm + wm * 32 + mt * 16 + (lane >> 2);
#pragma unroll
            for (int nt = 0; nt < 8; nt++) {
                const int n = bn + wn * 64 + nt * 8 + ((lane & 3) << 1);
                float2 b2 = *(const float2*)(bias + n);
                *(__half2*)(Oh + (size_t)m * N + n) = __halves2half2(
                    __float2half_rn(acc[mt][nt][0] + b2.x),
                    __float2half_rn(acc[mt][nt][1] + b2.y));
                *(__half2*)(Oh + (size_t)(m + 8) * N + n) = __halves2half2(
                    __float2half_rn(acc[mt][nt][2] + b2.x),
                    __float2half_rn(acc[mt][nt][3] + b2.y));
            }
        }
    } else {
#pragma unroll
        for (int mt = 0; mt < 2; mt++) {
            const int m = bm + wm * 32 + mt * 16 + (lane >> 2);
#pragma unroll
            for (int nt = 0; nt < 8; nt++) {
                const int n = bn + wn * 64 + nt * 8 + ((lane & 3) << 1);
                float2 b2 = *(const float2*)(bias + n);
                float2 o0, o1;
                o0.x = acc[mt][nt][0] + b2.x;
                o0.y = acc[mt][nt][1] + b2.y;
                o1.x = acc[mt][nt][2] + b2.x;
                o1.y = acc[mt][nt][3] + b2.y;
                if (R) {
                    float2 r0 = *(const float2*)(R + (size_t)m * N + n);
                    float2 r1 = *(const float2*)(R + (size_t)(m + 8) * N + n);
                    o0.x += r0.x; o0.y += r0.y;
                    o1.x += r1.x; o1.y += r1.y;
                }
                *(float2*)(C + (size_t)m * N + n) = o0;
                *(float2*)(C + (size_t)(m + 8) * N + n) = o1;
            }
        }
    }
}

// ================= RoPE: qkv fp16 -> fp16 q,k in [B,H,L,HD] =================
__global__ void rope_apply_half_kernel() {
    int idx = blockIdx.x * blockDim.x + threadIdx.x;
    if (idx >= BB * LL * HH * 64) return;
    int d = idx & 63;
    int h = (idx >> 6) & (HH - 1);
    int bl = idx >> 10;
    int b = bl >> 11;
    int l = bl & (LL - 1);
    float c = g_cos[l * 64 + d];
    float s = g_sin[l * 64 + d];
    size_t src = (size_t)bl * D3 + h * HD + d;
    size_t dst = ((size_t)(b * HH + h) * LL + l) * HD + d;

    float q1 = __half2float(g_qkvh[src]), q2 = __half2float(g_qkvh[src + 64]);
    g_qh[dst]      = __float2half_rn(q1 * c - q2 * s);
    g_qh[dst + 64] = __float2half_rn(q2 * c + q1 * s);

    size_t ks = src + DD;
    float k1 = __half2float(g_qkvh[ks]), k2 = __half2float(g_qkvh[ks + 64]);
    g_kh[dst]      = __float2half_rn(k1 * c - k2 * s);
    g_kh[dst + 64] = __float2half_rn(k2 * c + k1 * s);
}

// ================= V transpose (fp16) -> [B,H,HD,L] =================
__global__ void v_transpose_kernel() {
    __shared__ __half t[32][33];
    int l0 = blockIdx.x * 32, d0 = blockIdx.y * 32, bh = blockIdx.z;
    int b = bh >> 4, h = bh & 15;
    int tx = threadIdx.x, ty = threadIdx.y;
#pragma unroll
    for (int r = 0; r < 4; r++) {
        int l = ty + r * 8;
        t[l][tx] = g_qkvh[(size_t)(b * LL + l0 + l) * D3 + 2 * DD + h * HD + d0 + tx];
    }
    __syncthreads();
#pragma unroll
    for (int r = 0; r < 4; r++) {
        int d = ty + r * 8;
        g_vth[((size_t)bh * HD + d0 + d) * LL + l0 + tx] = t[tx][d];
    }
}

// ======= attention scores -> fp16 g_sh + per-(row, warp-slice) softmax partials =======
#define ATT_STG 16384
#define ATT_SMEM (3 * ATT_STG)

__global__ void __launch_bounds__(256, 2) attn_scores_mma_kernel() {
    extern __shared__ char sm[];
    const int jb = blockIdx.x, ib = blockIdx.y, bh = blockIdx.z;
    if (jb > ib) return;
    const int tid = threadIdx.x, lane = tid & 31, wid = tid >> 5;
    const int wm = wid & 3, wn = wid >> 2;
    const uint32_t smb = smem_u32(sm);

    const __half* Qh = g_qh + ((size_t)bh * LL + ib * 128) * HD;
    const __half* Kh = g_kh + ((size_t)bh * LL + jb * 128) * HD;

    const int rowA_base = wm * 32 + (lane & 15);
    const int rowB_base = wn * 64 + (lane & 7) + ((lane >> 4) << 3);
    const uint32_t xorw = (uint32_t)((lane & 6) << 3);

    float acc[2][8][4];
#pragma unroll
    for (int i = 0; i < 2; i++)
#pragma unroll
        for (int j = 0; j < 8; j++)
#pragma unroll
            for (int q = 0; q < 4; q++) acc[i][j][q] = 0.f;

    auto issue = [&](int c, int stg) {
        const uint32_t sb = smb + (uint32_t)(stg * ATT_STG);
        const int k0 = c * 32;
#pragma unroll
        for (int i = 0; i < 4; i++) {
            int u = tid + (i << 8);
            int row = (u >> 2) & 127;
            int seg = u & 3;
            const __half* src = (u < 512) ? Qh : Kh;
            uint32_t roff = (u < 512) ? 0u : 8192u;
            uint32_t dst = sb + roff + (uint32_t)(row * 64) +
                           (((uint32_t)(seg * 16)) ^ ((uint32_t)((row & 6) << 3)));
            CP_ASYNC16(dst, src + (size_t)row * HD + k0 + seg * 8);
        }
        CP_COMMIT();
    };

    issue(0, 0);
    issue(1, 1);
#pragma unroll 1
    for (int c = 0; c < 4; c++) {
        CP_WAIT1();
        __syncthreads();
        if (c + 2 < 4) issue(c + 2, (c + 2) % 3);
        else CP_COMMIT();
        const uint32_t stg = smb + (uint32_t)((c % 3) * ATT_STG);
#pragma unroll
        for (int kk = 0; kk < 2; kk++) {
            const uint32_t cbA = ((uint32_t)(kk * 32 + ((lane >> 4) << 4))) ^ xorw;
            const uint32_t cbB = ((uint32_t)(kk * 32 + (((lane >> 3) & 1) << 4))) ^ xorw;
            uint32_t ah[2][4], b4[4][4];
#pragma unroll
            for (int mt = 0; mt < 2; mt++)
                LDSM4(ah[mt], stg + 0 + (uint32_t)((rowA_base + mt * 16) * 64) + cbA);
#pragma unroll
            for (int bt = 0; bt < 4; bt++)
                LDSM4(b4[bt], stg + 8192 + (uint32_t)((rowB_base + bt * 16) * 64) + cbB);
#pragma unroll
            for (int mt = 0; mt < 2; mt++)
#pragma unroll
                for (int nt = 0; nt < 8; nt++) {
                    const uint32_t* b = b4[nt >> 1];
                    if (nt & 1) MMA_F16(acc[mt][nt], ah[mt], b[2], b[3]);
                    else        MMA_F16(acc[mt][nt], ah[mt], b[0], b[1]);
                }
        }
    }

    const float scale = 0.08838834764831845f;
#pragma unroll
    for (int mt = 0; mt < 2; mt++) {
        const int i0 = ib * 128 + wm * 32 + mt * 16 + (lane >> 2);
        float vr[2][16];
#pragma unroll
        for (int nt = 0; nt < 8; nt++) {
            const int j0 = jb * 128 + wn * 64 + nt * 8 + ((lane & 3) << 1);
            float s00 = (j0     <= i0)     ? acc[mt][nt][0] * scale : -30000.f;
            float s01 = (j0 + 1 <= i0)     ? acc[mt][nt][1] * scale : -30000.f;
            float s10 = (j0     <= i0 + 8) ? acc[mt][nt][2] * scale : -30000.f;
            float s11 = (j0 + 1 <= i0 + 8) ? acc[mt][nt][3] * scale : -30000.f;
            __half h00 = __float2half_rn(s00), h01 = __float2half_rn(s01);
            __half h10 = __float2half_rn(s10), h11 = __float2half_rn(s11);
            *(__half2*)(g_sh + ((size_t)bh * LL + i0) * LL + j0) = __halves2half2(h00, h01);
            *(__half2*)(g_sh + ((size_t)bh * LL + i0 + 8) * LL + j0) = __halves2half2(h10, h11);
            vr[0][nt * 2]     = __half2float(h00);
            vr[0][nt * 2 + 1] = __half2float(h01);
            vr[1][nt * 2]     = __half2float(h10);
            vr[1][nt * 2 + 1] = __half2float(h11);
        }
#pragma unroll
        for (int sr = 0; sr < 2; sr++) {
            float m = -1e30f;
#pragma unroll
            for (int k = 0; k < 16; k++) m = fmaxf(m, vr[sr][k]);
            m = fmaxf(m, __shfl_xor_sync(0xffffffffu, m, 1));
            m = fmaxf(m, __shfl_xor_sync(0xffffffffu, m, 2));
            float s = 0.f;
#pragma unroll
            for (int k = 0; k < 16; k++) s += __expf(vr[sr][k] - m);
            s += __shfl_xor_sync(0xffffffffu, s, 1);
            s += __shfl_xor_sync(0xffffffffu, s, 2);
            if ((lane & 3) == 0) {
                int row = i0 + sr * 8;
                size_t p = ((size_t)bh * LL + row) * 32 + jb * 2 + wn;
                g_pmax[p] = m;
                g_psum[p] = s;
            }
        }
    }
}

// ========== combine partials -> per-row M, 1/Sum ==========
__global__ void softmax_combine_kernel() {
    int idx = blockIdx.x * 256 + threadIdx.x;     // bh*2048 + row
    int i = idx & (LL - 1);
    int nb2 = ((i >> 7) + 1) << 1;
    const float* pm = g_pmax + (size_t)idx * 32;
    const float* ps = g_psum + (size_t)idx * 32;
    float M = -1e30f;
    for (int k = 0; k < nb2; k++) M = fmaxf(M, pm[k]);
    float S = 0.f;
    for (int k = 0; k < nb2; k++) S += ps[k] * __expf(pm[k] - M);
    g_rowm[idx] = M;
    g_rowinv[idx] = 1.f / S;
}

// ===== O = P@V with on-the-fly softmax transform of S (fp16), V via cp.async =====
__global__ void __launch_bounds__(256, 2) attn_pv_mma_kernel() {
    extern __shared__ char sm[];
    const int ib = blockIdx.x, bh = blockIdx.y;
    const int b = bh >> 4, h = bh & 15;
    const int tid = threadIdx.x, lane = tid & 31, wid = tid >> 5;
    const int wm = wid & 3, wn = wid >> 2;
    const uint32_t smb = smem_u32(sm);

    const __half* Vh = g_vth + (size_t)bh * HD * LL;

    // per-thread P rows (tile-local r0, r1 fixed across chunks)
    const int r0 = tid >> 2;
    const int r1 = (tid + 256) >> 2;
    const int seg = tid & 3;
    const int gi0 = ib * 128 + r0, gi1 = ib * 128 + r1;
    const float m0 = g_rowm[(size_t)bh * LL + gi0];
    const float iv0 = g_rowinv[(size_t)bh * LL + gi0];
    const float m1 = g_rowm[(size_t)bh * LL + gi1];
    const float iv1 = g_rowinv[(size_t)bh * LL + gi1];
    const __half* P0 = g_sh + ((size_t)bh * LL + gi0) * LL + seg * 8;
    const __half* P1 = g_sh + ((size_t)bh * LL + gi1) * LL + seg * 8;
    const uint32_t d0 = (uint32_t)(r0 * 64) + (((uint32_t)(seg * 16)) ^ ((uint32_t)((r0 & 6) << 3)));
    const uint32_t d1 = (uint32_t)(r1 * 64) + (((uint32_t)(seg * 16)) ^ ((uint32_t)((r1 & 6) << 3)));

    const int rowA_base = wm * 32 + (lane & 15);
    const int rowB_base = wn * 64 + (lane & 7) + ((lane >> 4) << 3);
    const uint32_t xorw = (uint32_t)((lane & 6) << 3);

    float acc[2][8][4];
#pragma unroll
    for (int i = 0; i < 2; i++)
#pragma unroll
        for (int j = 0; j < 8; j++)
#pragma unroll
            for (int q = 0; q < 4; q++) acc[i][j][q] = 0.f;

    auto issueV = [&](int c, int stg) {
        const uint32_t sb = smb + (uint32_t)(stg * ATT_STG) + 8192u;
        const int j0 = c * 32;
#pragma unroll
        for (int i = 2; i < 4; i++) {
            int u = tid + (i << 8);
            int row = (u >> 2) & 127;
            int sg = u & 3;
            uint32_t dst = sb + (uint32_t)(row * 64) +
                           (((uint32_t)(sg * 16)) ^ ((uint32_t)((row & 6) << 3)));
            CP_ASYNC16(dst, Vh + (size_t)row * LL + j0 + sg * 8);
        }
        CP_COMMIT();
    };

    auto xform = [&](uint4 pr, float m, float inv, uint32_t dst) {
        const __half2* hp = (const __half2*)&pr;
        uint4 o;
        __half2* op = (__half2*)&o;
#pragma unroll
        for (int k = 0; k < 4; k++) {
            float a = __low2float(hp[k]), c = __high2float(hp[k]);
            op[k] = __halves2half2(__float2half_rn(__expf(a - m) * inv),
                                   __float2half_rn(__expf(c - m) * inv));
        }
        STS128(dst, o);
    };

    const int NC = (ib + 1) * 4;
    // prologue: chunks 0,1
#pragma unroll
    for (int pc = 0; pc < 2; pc++) {
        uint4 p0 = *(const uint4*)(P0 + pc * 32);
        uint4 p1 = *(const uint4*)(P1 + pc * 32);
        issueV(pc, pc);
        xform(p0, m0, iv0, smb + (uint32_t)(pc * ATT_STG) + d0);
        xform(p1, m1, iv1, smb + (uint32_t)(pc * ATT_STG) + d1);
    }

#pragma unroll 1
    for (int c = 0; c < NC; c++) {
        CP_WAIT1();
        __syncthreads();
        uint4 p0n, p1n;
        const bool pre = (c + 2 < NC);
        if (pre) {
            p0n = *(const uint4*)(P0 + (c + 2) * 32);
            p1n = *(const uint4*)(P1 + (c + 2) * 32);
            issueV(c + 2, (c + 2) % 3);
        } else CP_COMMIT();

        const uint32_t stg = smb + (uint32_t)((c % 3) * ATT_STG);
#pragma unroll
        for (int kk = 0; kk < 2; kk++) {
            const uint32_t cbA = ((uint32_t)(kk * 32 + ((lane >> 4) << 4))) ^ xorw;
            const uint32_t cbB = ((uint32_t)(kk * 32 + (((lane >> 3) & 1) << 4))) ^ xorw;
            uint32_t ah[2][4], b4[4][4];
#pragma unroll
            for (int mt = 0; mt < 2; mt++)
                LDSM4(ah[mt], stg + 0 + (uint32_t)((rowA_base + mt * 16) * 64) + cbA);
#pragma unroll
            for (int bt = 0; bt < 4; bt++)
                LDSM4(b4[bt], stg + 8192 + (uint32_t)((rowB_base + bt * 16) * 64) + cbB);
#pragma unroll
            for (int mt = 0; mt < 2; mt++)
#pragma unroll
                for (int nt = 0; nt < 8; nt++) {
                    const uint32_t* bb = b4[nt >> 1];
                    if (nt & 1) MMA_F16(acc[mt][nt], ah[mt], bb[2], bb[3]);
                    else        MMA_F16(acc[mt][nt], ah[mt], bb[0], bb[1]);
                }
        }

        if (pre) {
            const uint32_t sbn = smb + (uint32_t)(((c + 2) % 3) * ATT_STG);
            xform(p0n, m0, iv0, sbn + d0);
            xform(p1n, m1, iv1, sbn + d1);
        }
    }

#pragma unroll
    for (int mt = 0; mt < 2; mt++) {
        const int qi = ib * 128 + wm * 32 + mt * 16 + (lane >> 2);
#pragma unroll
        for (int nt = 0; nt < 8; nt++) {
            const int d = wn * 64 + nt * 8 + ((lane & 3) << 1);
            size_t base0 = (size_t)(b * LL + qi) * DD + h * HD + d;
            size_t base1 = (size_t)(b * LL + qi + 8) * DD + h * HD + d;
            *(__half2*)(g_ah + base0) = __halves2half2(
                __float2half_rn(acc[mt][nt][0]), __float2half_rn(acc[mt][nt][1]));
            *(__half2*)(g_ah + base1) = __halves2half2(
                __float2half_rn(acc[mt][nt][2]), __float2half_rn(acc[mt][nt][3]));
        }
    }
}

// ================= launch =================
extern "C" void kernel_launch(void* const* d_in, const int* in_sizes, int n_in,
                              void* d_out, int out_size) {
    const float* x    = (const float*)d_in[0];
    const float* Wqkv = (const float*)d_in[1];
    const float* bqkv = (const float*)d_in[2];
    const float* Wo   = (const float*)d_in[3];
    const float* bo   = (const float*)d_in[4];
    const float* g1   = (const float*)d_in[5];
    const float* g2   = (const float*)d_in[6];
    const float* Wp   = (const float*)d_in[7];
    const float* bp   = (const float*)d_in[8];
    const float* Wff  = (const float*)d_in[9];
    const float* bff  = (const float*)d_in[10];
    float* out = (float*)d_out;

    __half *ah, *fh, *wq, *wo, *wp, *wf, *qkvh;
    float *x1;
    cudaGetSymbolAddress((void**)&ah,   g_ah);
    cudaGetSymbolAddress((void**)&fh,   g_fh);
    cudaGetSymbolAddress((void**)&wq,   g_WqkvT);
    cudaGetSymbolAddress((void**)&wo,   g_WoT);
    cudaGetSymbolAddress((void**)&wp,   g_WpT);
    cudaGetSymbolAddress((void**)&wf,   g_WffT);
    cudaGetSymbolAddress((void**)&qkvh, g_qkvh);
    cudaGetSymbolAddress((void**)&x1,   g_x1);

    cudaFuncSetAttribute(gemm_f16_kernel<0>,
                         cudaFuncAttributeMaxDynamicSharedMemorySize, GEMM_SMEM);
    cudaFuncSetAttribute(gemm_f16_kernel<1>,
                         cudaFuncAttributeMaxDynamicSharedMemorySize, GEMM_SMEM);
    cudaFuncSetAttribute(gemm_f16_kernel<2>,
                         cudaFuncAttributeMaxDynamicSharedMemorySize, GEMM_SMEM);
    cudaFuncSetAttribute(attn_scores_mma_kernel,
                         cudaFuncAttributeMaxDynamicSharedMemorySize, ATT_SMEM);
    cudaFuncSetAttribute(attn_pv_mma_kernel,
                         cudaFuncAttributeMaxDynamicSharedMemorySize, ATT_SMEM);

    dim3 tb(32, 8);

    rope_table_kernel<<<LL, 64>>>();
    transpose_half_kernel<<<dim3(D3 / 32, DD / 32), tb>>>(Wqkv, wq, DD, D3);
    rmsnorm_half_kernel<<<MROWS, 256>>>(x, g1, ah);

    // qkv (fp16 out) = h @ Wqkv + bqkv   (launch #4 — profiled)
    gemm_f16_kernel<2><<<dim3(MROWS / TM, D3 / TN), 256, GEMM_SMEM>>>(
        ah, wq, bqkv, nullptr, nullptr, qkvh, MROWS, D3, DD);

    {
        int total = BB * LL * HH * 64;
        rope_apply_half_kernel<<<(total + 255) / 256, 256>>>();
    }
    v_transpose_kernel<<<dim3(LL / 32, HD / 32, BB * HH), tb>>>();
    attn_scores_mma_kernel<<<dim3(LL / 128, LL / 128, BB * HH), 256, ATT_SMEM>>>();
    softmax_combine_kernel<<<(BB * HH * LL) / 256, 256>>>();
    attn_pv_mma_kernel<<<dim3(LL / 128, BB * HH), 256, ATT_SMEM>>>();

    transpose_half_kernel<<<dim3(DD / 32, DD / 32), tb>>>(Wo, wo, DD, DD);
    gemm_f16_kernel<0><<<dim3(MROWS / TM, DD / TN), 256, GEMM_SMEM>>>(
        ah, wo, bo, x, x1, nullptr, MROWS, DD, DD);

    rmsnorm_half_kernel<<<MROWS, 256>>>(x1, g2, ah);

    transpose_half_interleave_kernel<<<dim3(D8 / 32, DD / 32), tb>>>(Wp, wp, DD, D8);
    gemm_f16_kernel<1><<<dim3(MROWS / TM, D8 / TN), 256, GEMM_SMEM>>>(
        ah, wp, bp, nullptr, nullptr, fh, MROWS, D8, DD);

    transpose_half_kernel<<<dim3(DD / 32, D4 / 32), tb>>>(Wff, wf, D4, DD);
    gemm_f16_kernel<0><<<dim3(MROWS / TM, DD / TN), 256, GEMM_SMEM>>>(
        fh, wf, bff, x1, out, nullptr, MROWS, DD, D4);
}